// round 14
// baseline (speedup 1.0000x reference)
#include <cuda_runtime.h>
#include <cuda_fp16.h>
#include <mma.h>
#include <cstdint>
using namespace nvcuda;

#define B_   2
#define T_   2048
#define DM   1024
#define H_   16
#define DH   64
#define ROWS (B_*T_)       // 4096
#define CH   64
#define NCH  (T_/CH)       // 32
#define BH   (B_*H_)       // 32
#define GK   1024
#define NQKV 3072          // fused q|k|v column dim

// Scratch (allocation-free rule -> __device__ globals)
__device__ __align__(16) __half g_xh[ROWS*DM];            // x fp16
__device__ __align__(16) __half g_wqkv[DM*NQKV];          // [k][3072] = Wq|Wk|Wv packed
__device__ __align__(16) __half g_woh[DM*DM];             // Wo fp16
__device__ __align__(16) __half g_qkv[(size_t)ROWS*NQKV]; // fused q|k|v output
__device__ __align__(16) __half g_ah[ROWS*DM];            // attention output fp16
__device__ float g_kv[(size_t)BH*NCH*DH*DH];
__device__ float g_m [(size_t)BH*NCH*DH*DH];

__device__ __forceinline__ void cp16h(__half* dst, const __half* src) {
    uint32_t d = (uint32_t)__cvta_generic_to_shared(dst);
    asm volatile("cp.async.cg.shared.global [%0], [%1], 16;\n" :: "r"(d), "l"(src));
}

// ---------------------------------------------------------------------------
// Prepass A: fp32 -> fp16 contiguous (x).
// ---------------------------------------------------------------------------
__global__ void __launch_bounds__(256) tofp16(const float4* __restrict__ src,
                                              uint4* __restrict__ dst) {
    int i = blockIdx.x * 256 + threadIdx.x;
    float4 a = src[2 * i], b = src[2 * i + 1];
    __half h[8] = {__float2half_rn(a.x), __float2half_rn(a.y),
                   __float2half_rn(a.z), __float2half_rn(a.w),
                   __float2half_rn(b.x), __float2half_rn(b.y),
                   __float2half_rn(b.z), __float2half_rn(b.w)};
    dst[i] = *(uint4*)h;
}

// ---------------------------------------------------------------------------
// Prepass B: convert all 4 weight matrices. grid (512, 4).
//   m<3: pack into g_wqkv [k][3072];  m==3: contiguous g_woh.
// ---------------------------------------------------------------------------
__global__ void __launch_bounds__(256) conv_w(const float4* __restrict__ Wq,
                                              const float4* __restrict__ Wk,
                                              const float4* __restrict__ Wv,
                                              const float4* __restrict__ Wo) {
    const int m = blockIdx.y;
    const float4* src = (m == 0) ? Wq : (m == 1) ? Wk : (m == 2) ? Wv : Wo;
    int i = blockIdx.x * 256 + threadIdx.x;
    float4 a = src[2 * i], b = src[2 * i + 1];
    __half h[8] = {__float2half_rn(a.x), __float2half_rn(a.y),
                   __float2half_rn(a.z), __float2half_rn(a.w),
                   __float2half_rn(b.x), __float2half_rn(b.y),
                   __float2half_rn(b.z), __float2half_rn(b.w)};
    if (m < 3) {
        int e = i * 8;
        int kr = e >> 10, n = e & 1023;
        *(uint4*)(g_wqkv + (size_t)kr * NQKV + m * DM + n) = *(uint4*)h;
    } else {
        *((uint4*)g_woh + i) = *(uint4*)h;
    }
}

// ---------------------------------------------------------------------------
// fp16 GEMM, fp32 accumulate: C[M,NN] = A[M,GK] @ W[GK,NN].
// CTA tile 128x256, ktile 32, 3-stage cp.async, 8 warps (2x4 of 64x64).
// ---------------------------------------------------------------------------
#define KT2  32
#define LDA2 40     // 32 + 8 pad halves
#define LDB2 264    // 256 + 8 pad halves
#define ASZ2 (128*LDA2)     // 5120 halves
#define BSZ2 (KT2*LDB2)     // 8448 halves
#define STG  3
#define GSM  (STG*(ASZ2+BSZ2)*2)   // 81408 B

typedef wmma::fragment<wmma::matrix_a, 16, 16, 16, __half, wmma::row_major> HFragA;
typedef wmma::fragment<wmma::matrix_b, 16, 16, 16, __half, wmma::row_major> HFragB;

template <int NN, bool HALF_OUT>
__global__ void __launch_bounds__(256) gemm_h(const __half* __restrict__ A,
                                              const __half* __restrict__ W,
                                              void* __restrict__ Cv) {
    extern __shared__ __half smb[];
    __half* sA = smb;                 // STG x ASZ2
    __half* sB = smb + STG * ASZ2;    // STG x BSZ2

    const int row0 = blockIdx.y * 128;
    const int col0 = blockIdx.x * 256;
    const int tid  = threadIdx.x;
    const int w    = tid >> 5;
    const int lane = tid & 31;
    const int wr   = w & 1;           // 2 row groups of 64
    const int wc   = w >> 1;          // 4 col groups of 64

    wmma::fragment<wmma::accumulator, 16, 16, 16, float> acc[4][4];
#pragma unroll
    for (int i = 0; i < 4; i++)
#pragma unroll
        for (int j = 0; j < 4; j++) wmma::fill_fragment(acc[i][j], 0.0f);

    auto issue = [&](int kt, int buf) {
        const int k0 = kt * KT2;
#pragma unroll
        for (int i = 0; i < 2; i++) {            // A: 128x32 halves = 512 cp16
            int id = tid + i * 256;
            int r = id >> 2, c8 = (id & 3) * 8;
            cp16h(sA + buf * ASZ2 + r * LDA2 + c8, A + (size_t)(row0 + r) * GK + k0 + c8);
        }
#pragma unroll
        for (int i = 0; i < 4; i++) {            // B: 32x256 halves = 1024 cp16
            int id = tid + i * 256;
            int r = id >> 5, c8 = (id & 31) * 8;
            cp16h(sB + buf * BSZ2 + r * LDB2 + c8, W + (size_t)(k0 + r) * NN + col0 + c8);
        }
        asm volatile("cp.async.commit_group;\n");
    };

    const int NT = GK / KT2;          // 32
    issue(0, 0);
    issue(1, 1);
    for (int kt = 0; kt < NT; kt++) {
        if (kt + 1 < NT) asm volatile("cp.async.wait_group 1;\n");
        else             asm volatile("cp.async.wait_group 0;\n");
        __syncthreads();
        if (kt + 2 < NT) issue(kt + 2, (kt + 2) % STG);

        const int cur = kt % STG;
        const __half* Ac = sA + cur * ASZ2;
        const __half* Bc = sB + cur * BSZ2;
#pragma unroll
        for (int kk = 0; kk < 2; kk++) {
            HFragA a[4];
#pragma unroll
            for (int i = 0; i < 4; i++)
                wmma::load_matrix_sync(a[i], Ac + (wr * 64 + i * 16) * LDA2 + kk * 16, LDA2);
#pragma unroll
            for (int j = 0; j < 4; j++) {
                HFragB b;
                wmma::load_matrix_sync(b, Bc + (kk * 16) * LDB2 + wc * 64 + j * 16, LDB2);
#pragma unroll
                for (int i = 0; i < 4; i++)
                    wmma::mma_sync(acc[i][j], a[i], b, acc[i][j]);
            }
        }
    }
    __syncthreads();

    if constexpr (HALF_OUT) {
        // Per-warp staging: 64x20 fp32 = 5120 B each, 8 warps = 40960 B
        float* wf = (float*)smb + w * (64 * 20);
        __half* C = (__half*)Cv;
#pragma unroll
        for (int j = 0; j < 4; j++) {
#pragma unroll
            for (int i = 0; i < 4; i++)
                wmma::store_matrix_sync(wf + i * 16 * 20, acc[i][j], 20, wmma::mem_row_major);
            __syncwarp();
#pragma unroll
            for (int rr = 0; rr < 2; rr++) {
                int row = lane * 2 + rr;
                __half h[16];
#pragma unroll
                for (int e = 0; e < 16; e++) h[e] = __float2half_rn(wf[row * 20 + e]);
                __half* dst = C + (size_t)(row0 + wr * 64 + row) * NN + col0 + wc * 64 + j * 16;
                *(uint4*)dst       = ((uint4*)h)[0];
                *(uint4*)(dst + 8) = ((uint4*)h)[1];
            }
            __syncwarp();
        }
    } else {
        float* C = (float*)Cv;
#pragma unroll
        for (int i = 0; i < 4; i++)
#pragma unroll
            for (int j = 0; j < 4; j++)
                wmma::store_matrix_sync(C + (size_t)(row0 + wr * 64 + i * 16) * NN
                                          + col0 + wc * 64 + j * 16,
                                        acc[i][j], NN, wmma::mem_row_major);
    }
}

// ---------------------------------------------------------------------------
// Phase 1: per-chunk KV_c = K_c^T @ V_c (64x64, k=64), fp16 in / fp32 acc.
// ---------------------------------------------------------------------------
#define LDAh 72

__global__ void __launch_bounds__(128) chunk_kv() {
    __shared__ __half Ks[CH * LDAh];
    __shared__ __half Vs[CH * LDAh];
    const int ch = blockIdx.x, bh = blockIdx.y;
    const int b = bh >> 4, h = bh & 15;
    const int tid = threadIdx.x, w = tid >> 5;

    const __half* Kg = g_qkv + (size_t)(b * T_ + ch * CH) * NQKV + DM + h * DH;
    const __half* Vg = g_qkv + (size_t)(b * T_ + ch * CH) * NQKV + 2 * DM + h * DH;
#pragma unroll
    for (int i = 0; i < 4; i++) {
        int id = tid + i * 128;
        int r = id >> 3, c8 = (id & 7) * 8;
        *(uint4*)(Ks + r * LDAh + c8) = *(const uint4*)(Kg + (size_t)r * NQKV + c8);
        *(uint4*)(Vs + r * LDAh + c8) = *(const uint4*)(Vg + (size_t)r * NQKV + c8);
    }
    __syncthreads();

    wmma::fragment<wmma::accumulator, 16, 16, 16, float> acc[4];
#pragma unroll
    for (int i = 0; i < 4; i++) wmma::fill_fragment(acc[i], 0.0f);

#pragma unroll
    for (int kk = 0; kk < 4; kk++) {
        wmma::fragment<wmma::matrix_a, 16, 16, 16, __half, wmma::col_major> a;
        wmma::load_matrix_sync(a, Ks + (kk * 16) * LDAh + w * 16, LDAh);
#pragma unroll
        for (int nf = 0; nf < 4; nf++) {
            HFragB bb;
            wmma::load_matrix_sync(bb, Vs + (kk * 16) * LDAh + nf * 16, LDAh);
            wmma::mma_sync(acc[nf], a, bb, acc[nf]);
        }
    }

    float* out = g_kv + ((size_t)bh * NCH + ch) * DH * DH;
#pragma unroll
    for (int nf = 0; nf < 4; nf++)
        wmma::store_matrix_sync(out + (w * 16) * DH + nf * 16, acc[nf], DH,
                                wmma::mem_row_major);
}

// ---------------------------------------------------------------------------
// Phase 2: exclusive prefix over chunks (fp32 exact).
// ---------------------------------------------------------------------------
__global__ void __launch_bounds__(512) prefix_kv() {
    const int bh = blockIdx.y;
    const int e  = blockIdx.x * 512 + threadIdx.x;
    const size_t base = (size_t)bh * NCH * DH * DH;
    float run = 0.0f;
#pragma unroll
    for (int c = 0; c < NCH; c++) {
        g_m[base + (size_t)c * (DH * DH) + e] = run;
        run += g_kv[base + (size_t)c * (DH * DH) + e];
    }
}

// ---------------------------------------------------------------------------
// Phase 3: O_c = Q_c @ M_c + mask(Q_c K_c^T) @ V_c, fp16 MMA / fp32 acc.
// ---------------------------------------------------------------------------
#define ATTN_SMEM (5 * 64 * LDAh * 2 + 64 * 68 * 4)   // 63488 B

__global__ void __launch_bounds__(128) attn_chunk() {
    extern __shared__ __half smh[];
    __half* Qs = smh;
    __half* Ks = Qs + 64 * LDAh;
    __half* Vs = Ks + 64 * LDAh;
    __half* Ms = Vs + 64 * LDAh;
    __half* Sh = Ms + 64 * LDAh;
    float*  Ss = (float*)(Sh + 64 * LDAh);

    const int ch = blockIdx.x, bh = blockIdx.y;
    const int b = bh >> 4, h = bh & 15;
    const int t0 = ch * CH;
    const int tid = threadIdx.x, w = tid >> 5, lane = tid & 31;

    const __half* Qg = g_qkv + (size_t)(b * T_ + t0) * NQKV + h * DH;
    const __half* Kg = Qg + DM;
    const __half* Vg = Qg + 2 * DM;
    const float*  Mg = g_m + ((size_t)bh * NCH + ch) * DH * DH;

#pragma unroll
    for (int i = 0; i < 4; i++) {
        int id = tid + i * 128;
        int r = id >> 3, c8 = (id & 7) * 8;
        *(uint4*)(Qs + r * LDAh + c8) = *(const uint4*)(Qg + (size_t)r * NQKV + c8);
        *(uint4*)(Ks + r * LDAh + c8) = *(const uint4*)(Kg + (size_t)r * NQKV + c8);
        *(uint4*)(Vs + r * LDAh + c8) = *(const uint4*)(Vg + (size_t)r * NQKV + c8);
    }
#pragma unroll
    for (int i = 0; i < 8; i++) {
        int id = tid + i * 128;
        int r = id >> 4, c4 = (id & 15) * 4;
        float4 mv = *(const float4*)(Mg + id * 4);
        __half hm[4] = {__float2half_rn(mv.x), __float2half_rn(mv.y),
                        __float2half_rn(mv.z), __float2half_rn(mv.w)};
        *(uint2*)(Ms + r * LDAh + c4) = *(uint2*)hm;
    }
    __syncthreads();

    wmma::fragment<wmma::accumulator, 16, 16, 16, float> o[4];
#pragma unroll
    for (int i = 0; i < 4; i++) wmma::fill_fragment(o[i], 0.0f);

    // (a) O = Q @ M
#pragma unroll
    for (int kk = 0; kk < 4; kk++) {
        HFragA a;
        wmma::load_matrix_sync(a, Qs + (w * 16) * LDAh + kk * 16, LDAh);
#pragma unroll
        for (int nf = 0; nf < 4; nf++) {
            HFragB bb;
            wmma::load_matrix_sync(bb, Ms + (kk * 16) * LDAh + nf * 16, LDAh);
            wmma::mma_sync(o[nf], a, bb, o[nf]);
        }
    }

    // (b) S = Q @ K^T
    wmma::fragment<wmma::accumulator, 16, 16, 16, float> s_acc[4];
#pragma unroll
    for (int i = 0; i < 4; i++) wmma::fill_fragment(s_acc[i], 0.0f);
#pragma unroll
    for (int kk = 0; kk < 4; kk++) {
        HFragA a;
        wmma::load_matrix_sync(a, Qs + (w * 16) * LDAh + kk * 16, LDAh);
#pragma unroll
        for (int nf = 0; nf < 4; nf++) {
            wmma::fragment<wmma::matrix_b, 16, 16, 16, __half, wmma::col_major> bb;
            wmma::load_matrix_sync(bb, Ks + (nf * 16) * LDAh + kk * 16, LDAh);
            wmma::mma_sync(s_acc[nf], a, bb, s_acc[nf]);
        }
    }
#pragma unroll
    for (int nf = 0; nf < 4; nf++)
        wmma::store_matrix_sync(Ss + (w * 16) * 68 + nf * 16, s_acc[nf], 68,
                                wmma::mem_row_major);
    __syncwarp();

    // strictly-lower mask (keep col < row) + fp16 convert
#pragma unroll
    for (int i = 0; i < 16; i++) {
#pragma unroll
        for (int c2 = 0; c2 < 2; c2++) {
            int c = c2 * 32 + lane;
            float v = (c < w * 16 + i) ? Ss[(w * 16 + i) * 68 + c] : 0.0f;
            Sh[(w * 16 + i) * LDAh + c] = __float2half_rn(v);
        }
    }
    __syncwarp();

    // (c) O += S @ V
#pragma unroll
    for (int kk = 0; kk < 4; kk++) {
        HFragA a;
        wmma::load_matrix_sync(a, Sh + (w * 16) * LDAh + kk * 16, LDAh);
#pragma unroll
        for (int nf = 0; nf < 4; nf++) {
            HFragB bb;
            wmma::load_matrix_sync(bb, Vs + (kk * 16) * LDAh + nf * 16, LDAh);
            wmma::mma_sync(o[nf], a, bb, o[nf]);
        }
    }

    // Epilogue: O -> fp16 global
#pragma unroll
    for (int nf = 0; nf < 4; nf++)
        wmma::store_matrix_sync(Ss + (w * 16) * 68 + nf * 16, o[nf], 68,
                                wmma::mem_row_major);
    __syncwarp();

    __half* Hg = g_ah + (size_t)(b * T_ + t0 + w * 16) * DM + h * DH;
#pragma unroll
    for (int i = 0; i < 16; i++) {
#pragma unroll
        for (int c2 = 0; c2 < 2; c2++) {
            int c = c2 * 32 + lane;
            Hg[(size_t)i * DM + c] = __float2half_rn(Ss[(w * 16 + i) * 68 + c]);
        }
    }
}

// ---------------------------------------------------------------------------
extern "C" void kernel_launch(void* const* d_in, const int* in_sizes, int n_in,
                              void* d_out, int out_size) {
    const float* x  = (const float*)d_in[0];
    const float* Wq = (const float*)d_in[1];
    const float* Wk = (const float*)d_in[2];
    const float* Wv = (const float*)d_in[3];
    const float* Wo = (const float*)d_in[4];

    __half *xh, *woh, *qkv, *ah, *wqkv;
    cudaGetSymbolAddress((void**)&xh,   g_xh);
    cudaGetSymbolAddress((void**)&woh,  g_woh);
    cudaGetSymbolAddress((void**)&qkv,  g_qkv);
    cudaGetSymbolAddress((void**)&ah,   g_ah);
    cudaGetSymbolAddress((void**)&wqkv, g_wqkv);

    cudaFuncSetAttribute(gemm_h<NQKV, true>, cudaFuncAttributeMaxDynamicSharedMemorySize, GSM);
    cudaFuncSetAttribute(gemm_h<DM, false>,  cudaFuncAttributeMaxDynamicSharedMemorySize, GSM);
    cudaFuncSetAttribute(attn_chunk,         cudaFuncAttributeMaxDynamicSharedMemorySize, ATTN_SMEM);

    // Prepass (2 launches): x, all weights
    tofp16<<<ROWS * DM / 8 / 256, 256>>>((const float4*)x, (uint4*)xh);
    conv_w<<<dim3(DM * DM / 8 / 256, 4), 256>>>((const float4*)Wq, (const float4*)Wk,
                                                (const float4*)Wv, (const float4*)Wo);

    // Fused QKV GEMM: [4096,1024] @ [1024,3072] -> fp16
    gemm_h<NQKV, true><<<dim3(NQKV / 256, ROWS / 128), 256, GSM>>>(xh, wqkv, qkv);

    chunk_kv<<<dim3(NCH, BH), 128>>>();
    prefix_kv<<<dim3(8, BH), 512>>>();
    attn_chunk<<<dim3(NCH, BH), 128, ATTN_SMEM>>>();

    // Output projection: [4096,1024] @ [1024,1024] -> fp32 d_out
    gemm_h<DM, false><<<dim3(DM / 256, ROWS / 128), 256, GSM>>>(ah, woh, (float*)d_out);
}